// round 15
// baseline (speedup 1.0000x reference)
#include <cuda_runtime.h>

#define HN 4096

constexpr int TH = 128;                    // output rows per warp-tile
constexpr int OUTW = 112;                  // output cols per warp strip
constexpr int NSTRIPS = 37;
constexpr int WPB = 2;                     // 64-thread blocks
constexpr int NBANDS = HN / TH;            // 32
constexpr int NTILES = NSTRIPS * NBANDS;   // 1184
constexpr int NBLK = NTILES / WPB;         // 592
constexpr int N_INT = 35 * 30;             // 1050 interior tiles
constexpr int N_EDGE = NTILES - N_INT;     // 134, spread 1-per-block on warp 1

__device__ double g_accs[8 * 16];   // 8 slots, 128B apart; reset by last block
__device__ unsigned g_done;

static __device__ __forceinline__ float4 ld4p(const float* p, bool v) {
    float4 r = make_float4(0.f, 0.f, 0.f, 0.f);
    if (v) r = *reinterpret_cast<const float4*>(p);
    return r;
}

// 4-tap window sum over columns: g[c] = v[c-1]+v[c]+v[c+1]+v[c+2]
static __device__ __forceinline__ float4 hwin(float4 v, float vl, float vr0, float vr1) {
    float4 g;
    g.x = vl + v.x + v.y + v.z;
    g.y = g.x - vl + v.w;
    g.z = g.y - v.x + vr0;
    g.w = g.z - v.y + vr1;
    return g;
}

static __device__ __forceinline__ float maskf(float x, unsigned m) {
    return __uint_as_float(__float_as_uint(x) & m);
}

// pack two floats as bf16x2 (a -> lo half, b -> hi half)
static __device__ __forceinline__ unsigned bpack(float a, float b) {
    unsigned r;
    asm("cvt.rn.bf16x2.f32 %0, %1, %2;" : "=r"(r) : "f"(b), "f"(a));
    return r;
}
static __device__ __forceinline__ float bf_lo(unsigned p) {
    return __uint_as_float(p << 16);
}
static __device__ __forceinline__ float bf_hi(unsigned p) {
    return __uint_as_float(p & 0xffff0000u);
}

template<bool EDGE>
static __device__ __forceinline__ float tile_compute(
    const float* __restrict__ X, const float* __restrict__ Y,
    int strip, int tyt, int lane)
{
    const int ty0 = tyt * TH;
    const long col0 = (long)strip * OUTW - 8 + 4 * lane;
    const bool ld_ok = EDGE ? ((col0 >= 0) && (col0 + 3 < HN)) : true;
    const unsigned mCb = EDGE ? ((lane >= 1 && lane <= 30 && ld_ok) ? ~0u : 0u) : ~0u;
    const float mO = ((lane >= 2 && lane <= 29) && ld_ok) ? 1.f : 0.f;
    const float mOn = -mO;
    const int i0 = ty0 - 8;   // multiple of 4

    // pX/pY track the prefetch row (i+6) of the current step
    const float* pX = X + col0 + (long)(i0 + 6) * HN;
    const float* pY = Y + col0 + (long)(i0 + 6) * HN;

    // 2-deep prefetch, phase-rotated
    float4 xs[2], ys[2];
    {
        bool v4 = EDGE ? (ld_ok && (unsigned)(i0 + 4) < HN) : true;
        bool v5 = EDGE ? (ld_ok && (unsigned)(i0 + 5) < HN) : true;
        xs[0] = ld4p(pX - 2 * HN, v4); ys[0] = ld4p(pY - 2 * HN, v4);
        xs[1] = ld4p(pX - 1 * HN, v5); ys[1] = ld4p(pY - 1 * HN, v5);
    }

    // rings: raw rows (slot = row index & 3) and centered rows
    float4 rx[4], ry[4], rc1[4], rc2[4];
    float4 Vx, Vy, Vi, Vj, Vc;
    {
        float4 z = make_float4(0.f, 0.f, 0.f, 0.f);
#pragma unroll
        for (int s = 0; s < 4; ++s) { rx[s] = z; ry[s] = z; rc1[s] = z; rc2[s] = z; }
        Vx = Vy = Vi = Vj = Vc = z;
    }

    float acc = 0.f;   // accumulates -L over valid output pixels

#define STEP(T, S, DO_OUT) do {                                                  \
    const int i = i0 + (T) + (S); (void)i;                                       \
    const int p_ = (S) & 1;                                                      \
    float4 xc = xs[p_], yc = ys[p_];                                             \
    {   bool v6 = EDGE ? (ld_ok && (unsigned)(i + 6) < HN) : true;               \
        xs[p_] = ld4p(pX, v6); ys[p_] = ld4p(pY, v6);                            \
        pX += HN; pY += HN; }                                                    \
    /* rolling vertical raw sums: +row(i+4), -row(i) (ring slot S) */            \
    {   float4 xo = rx[(S)]; rx[(S)] = xc;                                       \
        float4 yo = ry[(S)]; ry[(S)] = yc;                                       \
        Vx.x += xc.x - xo.x; Vx.y += xc.y - xo.y;                                \
        Vx.z += xc.z - xo.z; Vx.w += xc.w - xo.w;                                \
        Vy.x += yc.x - yo.x; Vy.y += yc.y - yo.y;                                \
        Vy.z += yc.z - yo.z; Vy.w += yc.w - yo.w; }                              \
    float4 x2 = rx[((S) + 2) & 3], y2 = ry[((S) + 2) & 3];  /* row i+2 */        \
    /* packed boundary shuffles: (Vx,Vy) pairs in one bf16x2 payload */          \
    unsigned pw_ = bpack(Vx.w, Vy.w);                                            \
    unsigned pa_ = bpack(Vx.x, Vy.x);                                            \
    unsigned pb_ = bpack(Vx.y, Vy.y);                                            \
    unsigned sl_  = __shfl_up_sync(0xffffffffu, pw_, 1);                         \
    unsigned sr0_ = __shfl_down_sync(0xffffffffu, pa_, 1);                       \
    unsigned sr1_ = __shfl_down_sync(0xffffffffu, pb_, 1);                       \
    float4 mx = hwin(Vx, bf_lo(sl_), bf_lo(sr0_), bf_lo(sr1_));                  \
    float4 my = hwin(Vy, bf_hi(sl_), bf_hi(sr0_), bf_hi(sr1_));                  \
    unsigned rmask = EDGE ? (((unsigned)(i + 2) < HN) ? mCb : 0u) : ~0u;         \
    float4 c1, c2;                                                               \
    c1.x = maskf(fmaf(mx.x, -0.0625f, x2.x), rmask);                             \
    c1.y = maskf(fmaf(mx.y, -0.0625f, x2.y), rmask);                             \
    c1.z = maskf(fmaf(mx.z, -0.0625f, x2.z), rmask);                             \
    c1.w = maskf(fmaf(mx.w, -0.0625f, x2.w), rmask);                             \
    c2.x = maskf(fmaf(my.x, -0.0625f, y2.x), rmask);                             \
    c2.y = maskf(fmaf(my.y, -0.0625f, y2.y), rmask);                             \
    c2.z = maskf(fmaf(my.z, -0.0625f, y2.z), rmask);                             \
    c2.w = maskf(fmaf(my.w, -0.0625f, y2.w), rmask);                             \
    /* rolling vertical sig sums over product rows i-1..i+2; ring stores c */    \
    {   const int sl = ((S) + 2) & 3;                                            \
        float4 o1 = rc1[sl], o2 = rc2[sl];                                       \
        rc1[sl] = c1; rc2[sl] = c2;                                              \
        Vi.x = fmaf(c1.x, c1.x, fmaf(o1.x, -o1.x, Vi.x));                        \
        Vi.y = fmaf(c1.y, c1.y, fmaf(o1.y, -o1.y, Vi.y));                        \
        Vi.z = fmaf(c1.z, c1.z, fmaf(o1.z, -o1.z, Vi.z));                        \
        Vi.w = fmaf(c1.w, c1.w, fmaf(o1.w, -o1.w, Vi.w));                        \
        Vj.x = fmaf(c2.x, c2.x, fmaf(o2.x, -o2.x, Vj.x));                        \
        Vj.y = fmaf(c2.y, c2.y, fmaf(o2.y, -o2.y, Vj.y));                        \
        Vj.z = fmaf(c2.z, c2.z, fmaf(o2.z, -o2.z, Vj.z));                        \
        Vj.w = fmaf(c2.w, c2.w, fmaf(o2.w, -o2.w, Vj.w));                        \
        Vc.x = fmaf(c1.x, c2.x, fmaf(o1.x, -o2.x, Vc.x));                        \
        Vc.y = fmaf(c1.y, c2.y, fmaf(o1.y, -o2.y, Vc.y));                        \
        Vc.z = fmaf(c1.z, c2.z, fmaf(o1.z, -o2.z, Vc.z));                        \
        Vc.w = fmaf(c1.w, c2.w, fmaf(o1.w, -o2.w, Vc.w));                        \
    }                                                                            \
    if (DO_OUT) {  /* compile-time: output row i */                              \
        unsigned qw_ = bpack(Vi.w, Vj.w);                                        \
        unsigned qa_ = bpack(Vi.x, Vj.x);                                        \
        unsigned qb_ = bpack(Vi.y, Vj.y);                                        \
        unsigned tw_ = __shfl_up_sync(0xffffffffu, qw_, 1);                      \
        unsigned ta_ = __shfl_down_sync(0xffffffffu, qa_, 1);                    \
        unsigned tb_ = __shfl_down_sync(0xffffffffu, qb_, 1);                    \
        float cl  = __shfl_up_sync(0xffffffffu, Vc.w, 1);                        \
        float cr0 = __shfl_down_sync(0xffffffffu, Vc.x, 1);                      \
        float cr1 = __shfl_down_sync(0xffffffffu, Vc.y, 1);                      \
        float4 sii = hwin(Vi, bf_lo(tw_), bf_lo(ta_), bf_lo(tb_));               \
        float4 sjj = hwin(Vj, bf_hi(tw_), bf_hi(ta_), bf_hi(tb_));               \
        float4 sij = hwin(Vc, cl, cr0, cr1);                                     \
        { float a = fmaxf(sii.x, 1e-20f), b = fmaxf(sjj.x, 1e-20f);              \
          float L = sij.x * rsqrtf(a * b);                                       \
          acc = fmaf(L, mOn, acc); }                                             \
        { float a = fmaxf(sii.y, 1e-20f), b = fmaxf(sjj.y, 1e-20f);              \
          float L = sij.y * rsqrtf(a * b);                                       \
          acc = fmaf(L, mOn, acc); }                                             \
        { float a = fmaxf(sii.z, 1e-20f), b = fmaxf(sjj.z, 1e-20f);              \
          float L = sij.z * rsqrtf(a * b);                                       \
          acc = fmaf(L, mOn, acc); }                                             \
        { float a = fmaxf(sii.w, 1e-20f), b = fmaxf(sjj.w, 1e-20f);              \
          float L = sij.w * rsqrtf(a * b);                                       \
          acc = fmaf(L, mOn, acc); }                                             \
    }                                                                            \
} while (0)

    // ---- warmup: 8 steps, no output, no per-step branch ----
    STEP(0, 0, false); STEP(0, 1, false); STEP(0, 2, false); STEP(0, 3, false);
    STEP(4, 0, false); STEP(4, 1, false); STEP(4, 2, false); STEP(4, 3, false);

    // ---- steady state: TH steps, unconditional output ----
#pragma unroll 1
    for (int T = 8; T < TH + 8; T += 4) {
        STEP(T, 0, true);
        STEP(T, 1, true);
        STEP(T, 2, true);
        STEP(T, 3, true);
    }
#undef STEP

    // +1 per valid output pixel, plus accumulated (-L)
    return fmaf((float)(TH * 4), mO, acc);
}

__global__ void __launch_bounds__(WPB * 32, 8)
xcorr_kernel(const float* __restrict__ X, const float* __restrict__ Y,
             float* __restrict__ out) {
    const int lane = threadIdx.x & 31;
    const int warp = threadIdx.x >> 5;
    const int b = blockIdx.x;

    float tot;
    if (warp == 1 && b < N_EDGE) {
        // one edge tile per early block -> edge work spread across SMs
        const int e = b;                      // 0..133
        int strip, band;
        if (e < 37)      { strip = e;       band = 0; }
        else if (e < 74) { strip = e - 37;  band = NBANDS - 1; }
        else { int e2 = e - 74; strip = (e2 & 1) ? (NSTRIPS - 1) : 0; band = 1 + (e2 >> 1); }
        tot = tile_compute<true>(X, Y, strip, band, lane);
    } else {
        // interior tiles: strips 1..35, bands 1..30 (1050 total)
        const int idx = (b < N_EDGE) ? b : (2 * b - N_EDGE + warp);
        const int strip = 1 + idx % 35;
        const int band = 1 + idx / 35;
        tot = tile_compute<false>(X, Y, strip, band, lane);
    }

#pragma unroll
    for (int o = 16; o; o >>= 1) tot += __shfl_xor_sync(0xffffffffu, tot, o);

    __shared__ float wsum[WPB];
    if (lane == 0) wsum[warp] = tot;
    __syncthreads();
    if (threadIdx.x == 0) {
        float s = wsum[0] + wsum[1];
        atomicAdd(&g_accs[(blockIdx.x & 7) * 16], (double)s);
        __threadfence();
        unsigned done = atomicAdd(&g_done, 1u);
        if (done == (unsigned)(NBLK - 1)) {   // last block finalizes
            double m = 0.0;
#pragma unroll
            for (int k = 0; k < 8; ++k)
                m += atomicAdd(&g_accs[k * 16], 0.0);   // coherent read
            m *= (1.0 / ((double)HN * (double)HN));
            out[0] = (float)m;
            out[1] = (float)m;
#pragma unroll
            for (int k = 0; k < 8; ++k) g_accs[k * 16] = 0.0;  // reset for replay
            g_done = 0u;
        }
    }
}

extern "C" void kernel_launch(void* const* d_in, const int* in_sizes, int n_in,
                              void* d_out, int out_size) {
    const float* X = (const float*)d_in[0];   // outputs
    const float* Y = (const float*)d_in[1];   // labels
    xcorr_kernel<<<NBLK, WPB * 32>>>(X, Y, (float*)d_out);
}